// round 2
// baseline (speedup 1.0000x reference)
#include <cuda_runtime.h>
#include <math.h>

#define BB 8
#define LL 48000
#define VV 28
#define QQ 256
#define CC 256
#define TT 960          // L / 50
#define NGD 29          // V + 1

// ---------------- scratch (static __device__, no allocation) ----------------
__device__ int    g_preds[BB * TT];
__device__ float  g_Wd2T[10 * 256 * 256];     // [j][c][q]
__device__ float  g_M[NGD * 5 * 10 * 256];    // [i][j2][j][q]
__device__ float  g_LSE[NGD * 5 * 10];        // [i][j2][j]
__device__ double g_prec[1500];
__device__ double g_pkl[1500];

// ---------------- encoder: conv1 + relu6 + conv2 + gumbel argmax ----------------
// grid 240 = 8 b * 30 chunks(32 t). block 256 = 32 t-lanes x 8 c-groups.
#define W2STRIDE 140              // 140 mod 32 = 12 -> conflict-free float4 per warp
#define W2S_OFF 0
#define W1S_OFF (256 * W2STRIDE)                 // W1 stride 13 (13 mod 32 odd-ish, distinct banks)
#define XS_OFF  (W1S_OFF + 256 * 13)
#define B1S_OFF (XS_OFF + 32 * 50)
#define B2S_OFF (B1S_OFF + 256)
#define ENC_SMEM_FLOATS (B2S_OFF + 32)
#define ENC_SMEM_BYTES  (ENC_SMEM_FLOATS * 4)

__global__ __launch_bounds__(256, 1)
void k_encode(const float* __restrict__ x, const float* __restrict__ gumbel,
              const float* __restrict__ W1, const float* __restrict__ b1,
              const float* __restrict__ W2, const float* __restrict__ b2)
{
    extern __shared__ float sm[];
    float* W2s = sm + W2S_OFF;
    float* W1s = sm + W1S_OFF;
    float* xs  = sm + XS_OFF;
    float* b1s = sm + B1S_OFF;
    float* b2s = sm + B2S_OFF;

    const int tid = threadIdx.x;
    const int b   = blockIdx.x / 30;
    const int t0  = (blockIdx.x % 30) * 32;

    // stage weights: coalesced global reads
    for (int lin = tid; lin < 28 * 256 * 5; lin += 256) {
        int o = lin / 1280, rem = lin % 1280;
        int c = rem / 5,    kk  = rem % 5;
        W2s[c * W2STRIDE + kk * 28 + o] = W2[lin];
    }
    for (int lin = tid; lin < 2560; lin += 256)
        W1s[(lin / 10) * 13 + (lin % 10)] = W1[lin];
    for (int lin = tid; lin < 32 * 50; lin += 256)
        xs[lin] = x[b * LL + t0 * 50 + lin];
    b1s[tid] = b1[tid];
    if (tid < 28) b2s[tid] = b2[tid];
    __syncthreads();

    const int tl = tid >> 3;      // local t (0..31)
    const int cg = tid & 7;       // channel group (0..7)
    const int t  = t0 + tl;

    float xr[50];
#pragma unroll
    for (int j = 0; j < 50; j++) xr[j] = xs[tl * 50 + j];

    float acc[28];
#pragma unroll
    for (int o = 0; o < 28; o++) acc[o] = 0.f;

#pragma unroll 2
    for (int ci = 0; ci < 32; ci++) {
        const int c = cg + 8 * ci;
        const float* w1row = &W1s[c * 13];
        float h[5];
#pragma unroll
        for (int kk = 0; kk < 5; kk++) {
            float s = b1s[c];
#pragma unroll
            for (int k = 0; k < 10; k++)
                s += xr[kk * 10 + k] * w1row[k];
            h[kk] = fminf(fmaxf(s, 0.f), 6.f);      // relu6
        }
        const float* wrow = &W2s[c * W2STRIDE];
#pragma unroll
        for (int kk = 0; kk < 5; kk++) {
            const float hv = h[kk];
#pragma unroll
            for (int og = 0; og < 7; og++) {
                float4 w = *(const float4*)(wrow + kk * 28 + og * 4);
                acc[og * 4 + 0] += hv * w.x;
                acc[og * 4 + 1] += hv * w.y;
                acc[og * 4 + 2] += hv * w.z;
                acc[og * 4 + 3] += hv * w.w;
            }
        }
    }

    // reduce the 8 c-groups (lane bits 0..2)
#pragma unroll
    for (int o = 0; o < 28; o++) {
        acc[o] += __shfl_xor_sync(0xffffffffu, acc[o], 1);
        acc[o] += __shfl_xor_sync(0xffffffffu, acc[o], 2);
        acc[o] += __shfl_xor_sync(0xffffffffu, acc[o], 4);
    }

    if (cg == 0) {
        const float* g = gumbel + (b * TT + t) * VV;
        float best = -1e30f; int bi = 0;
#pragma unroll
        for (int o = 0; o < 28; o++) {
            float v = acc[o] + b2s[o] + g[o];
            if (v > best) { best = v; bi = o; }    // first-max = jnp.argmax
        }
        g_preds[b * TT + t] = bi;
    }
}

// ---------------- transpose Wd2 (C,Q,K1) -> [j][c][q] ----------------
__global__ __launch_bounds__(256)
void k_transpose(const float* __restrict__ Wd2)
{
    const int c = blockIdx.x;
    const float* src = Wd2 + c * 2560;
    for (int lin = threadIdx.x; lin < 2560; lin += 256) {
        int q = lin / 10, j = lin % 10;
        g_Wd2T[j * 65536 + c * 256 + q] = src[lin];
    }
}

// ---------------- decoder table M[i][j2][j][q] + fused logsumexp over q ----------------
// grid 290 = 29 i * 10 j, 256 threads (= q)
__global__ __launch_bounds__(256)
void k_table(const float* __restrict__ Wd1, const float* __restrict__ bd1,
             const float* __restrict__ bd2)
{
    __shared__ float rv[5 * 256];
    __shared__ float red[8];
    const int i   = blockIdx.x / 10;
    const int j   = blockIdx.x % 10;
    const int tid = threadIdx.x;

    // rv[j2][c] = clip(Wd1[i,c,j2] + bd1[c], 0, 6); i==28 is the masked (z=0) row
    for (int lin = tid; lin < 1280; lin += 256) {
        int c = lin / 5, j2 = lin % 5;
        float w = (i < VV) ? Wd1[i * 1280 + lin] : 0.f;
        rv[j2 * 256 + c] = fminf(fmaxf(w + bd1[c], 0.f), 6.f);
    }
    __syncthreads();

    float acc[5] = {0.f, 0.f, 0.f, 0.f, 0.f};
    const float* wt = g_Wd2T + j * 65536 + tid;     // coalesced across q
#pragma unroll 4
    for (int c = 0; c < 256; c++) {
        float w = wt[c * 256];
#pragma unroll
        for (int j2 = 0; j2 < 5; j2++)
            acc[j2] += rv[j2 * 256 + c] * w;
    }
#pragma unroll
    for (int j2 = 0; j2 < 5; j2++)
        g_M[((i * 5 + j2) * 10 + j) * 256 + tid] = acc[j2];

    // LSE over q (threads) for each j2
    const float bdq  = bd2[tid];
    const int   lane = tid & 31, wid = tid >> 5;
    for (int j2 = 0; j2 < 5; j2++) {
        float v = acc[j2] + bdq;
        float m = v;
        for (int s = 16; s > 0; s >>= 1) m = fmaxf(m, __shfl_xor_sync(0xffffffffu, m, s));
        if (lane == 0) red[wid] = m;
        __syncthreads();
        float mAll = red[0];
#pragma unroll
        for (int w2 = 1; w2 < 8; w2++) mAll = fmaxf(mAll, red[w2]);
        __syncthreads();                        // everyone done reading red
        float e = expf(v - mAll);
        for (int s = 16; s > 0; s >>= 1) e += __shfl_xor_sync(0xffffffffu, e, s);
        if (lane == 0) red[wid] = e;
        __syncthreads();
        if (tid == 0) {
            float ssum = 0.f;
#pragma unroll
            for (int w2 = 0; w2 < 8; w2++) ssum += red[w2];
            g_LSE[(i * 5 + j2) * 10 + j] = mAll + logf(ssum);
        }
        __syncthreads();
    }
}

// ---------------- loss: mu-law target + table gather (rec) + KL ----------------
__global__ __launch_bounds__(256)
void k_loss(const float* __restrict__ x, const int* __restrict__ x_sl,
            const float* __restrict__ ngrams, const float* __restrict__ bd2)
{
    __shared__ double sred[8];
    const int tid = threadIdx.x;
    const int gid = blockIdx.x * 256 + tid;         // 0..383999
    const int b   = gid / LL, l = gid % LL;
    const int sl  = x_sl[b];
    const int zsl = sl / 50;
    const int t   = l / 50;

    double rec = 0.0, kl = 0.0;

    if (l < sl) {
        const float xv = x[gid];
        float y  = log1pf(255.f * fabsf(xv)) / 5.5451774444795625f;
        y = copysignf(y, xv);
        int tq = (int)floorf((y + 1.0f) * 0.5f * 256.0f);
        tq = min(max(tq, 0), 255);

        const int j2 = (l / 10) % 5;
        const int j  = l % 10;
        const int i  = (t < zsl) ? g_preds[b * TT + t] : 28;
        const int cell = (i * 5 + j2) * 10 + j;
        float lp = g_M[cell * 256 + tq] + bd2[tq] - g_LSE[cell];
        rec = -(double)lp;
    }

    if ((l % 50) == 0 && t < zsl) {
        const int p  = g_preds[b * TT + t];
        const int a0 = (t >= 2) ? g_preds[b * TT + t - 2] : 28;
        const int a1 = (t >= 1) ? g_preds[b * TT + t - 1] : 28;
        const float pr = ngrams[(a0 * 29 + a1) * 28 + p];
        kl = (double)logf(1.0f / (pr + 1e-10f) + 1e-10f);
    }

    // deterministic block reduce
    const int lane = tid & 31, wid = tid >> 5;
    for (int s = 16; s > 0; s >>= 1) {
        rec += __shfl_down_sync(0xffffffffu, rec, s);
        kl  += __shfl_down_sync(0xffffffffu, kl,  s);
    }
    if (lane == 0) sred[wid] = rec;
    __syncthreads();
    if (tid == 0) {
        double r = 0.0;
#pragma unroll
        for (int w2 = 0; w2 < 8; w2++) r += sred[w2];
        g_prec[blockIdx.x] = r;
    }
    __syncthreads();
    if (lane == 0) sred[wid] = kl;
    __syncthreads();
    if (tid == 0) {
        double k = 0.0;
#pragma unroll
        for (int w2 = 0; w2 < 8; w2++) k += sred[w2];
        g_pkl[blockIdx.x] = k;
    }
}

// ---------------- final fixed-order reduction ----------------
__global__ __launch_bounds__(256)
void k_final(const int* __restrict__ x_sl, float* __restrict__ out)
{
    __shared__ double sr[8], sk[8];
    const int tid = threadIdx.x;
    double r = 0.0, k = 0.0;
    for (int i = tid; i < 1500; i += 256) { r += g_prec[i]; k += g_pkl[i]; }
    const int lane = tid & 31, wid = tid >> 5;
    for (int s = 16; s > 0; s >>= 1) {
        r += __shfl_down_sync(0xffffffffu, r, s);
        k += __shfl_down_sync(0xffffffffu, k, s);
    }
    if (lane == 0) { sr[wid] = r; sk[wid] = k; }
    __syncthreads();
    if (tid == 0) {
        double R = 0.0, K = 0.0;
#pragma unroll
        for (int w2 = 0; w2 < 8; w2++) { R += sr[w2]; K += sk[w2]; }
        long long sx = 0, sz = 0;
#pragma unroll
        for (int b = 0; b < BB; b++) { sx += x_sl[b]; sz += x_sl[b] / 50; }
        out[0] = (float)(R / (double)sx + K / (double)sz);
    }
}

// ---------------- launch ----------------
extern "C" void kernel_launch(void* const* d_in, const int* in_sizes, int n_in,
                              void* d_out, int out_size)
{
    const float* x      = (const float*)d_in[0];
    const int*   x_sl   = (const int*)  d_in[1];
    const float* ngrams = (const float*)d_in[4];
    const float* gumbel = (const float*)d_in[5];
    const float* W1     = (const float*)d_in[6];
    const float* b1     = (const float*)d_in[7];
    const float* W2     = (const float*)d_in[8];
    const float* b2     = (const float*)d_in[9];
    const float* Wd1    = (const float*)d_in[10];
    const float* bd1    = (const float*)d_in[11];
    const float* Wd2    = (const float*)d_in[12];
    const float* bd2    = (const float*)d_in[13];
    float* out = (float*)d_out;

    cudaFuncSetAttribute(k_encode, cudaFuncAttributeMaxDynamicSharedMemorySize,
                         ENC_SMEM_BYTES);

    k_encode<<<240, 256, ENC_SMEM_BYTES>>>(x, gumbel, W1, b1, W2, b2);
    k_transpose<<<256, 256>>>(Wd2);
    k_table<<<290, 256>>>(Wd1, bd1, bd2);
    k_loss<<<1500, 256>>>(x, x_sl, ngrams, bd2);
    k_final<<<1, 256>>>(x_sl, out);
}

// round 3
// speedup vs baseline: 1.0201x; 1.0201x over previous
#include <cuda_runtime.h>
#include <math.h>

#define BB 8
#define LL 48000
#define VV 28
#define QQ 256
#define CC 256
#define TT 960          // L / 50
#define NGD 29          // V + 1

// ---------------- scratch ----------------
__device__ int    g_preds[BB * TT];
__device__ float  g_Wd2T[10 * 256 * 256];     // [j][c][q]
__device__ float  g_M[NGD * 5 * 10 * 256];    // [i][j2][j][q]  (holds logprob: M + bd2 - LSE)
__device__ double g_prec[1500];
__device__ double g_pkl[1500];

// ---------------- f32x2 helpers ----------------
__device__ __forceinline__ void fma2(unsigned long long& d, unsigned long long a,
                                     unsigned long long b, unsigned long long c) {
    asm("fma.rn.f32x2 %0, %1, %2, %3;" : "=l"(d) : "l"(a), "l"(b), "l"(c));
}
__device__ __forceinline__ void add2(unsigned long long& d, unsigned long long a,
                                     unsigned long long b) {
    asm("add.rn.f32x2 %0, %1, %2;" : "=l"(d) : "l"(a), "l"(b));
}
__device__ __forceinline__ unsigned long long bcast2(float v) {
    unsigned long long r;
    asm("mov.b64 %0, {%1, %1};" : "=l"(r) : "f"(v));
    return r;
}
__device__ __forceinline__ void unpack2(unsigned long long v, float& lo, float& hi) {
    asm("mov.b64 {%0, %1}, %2;" : "=f"(lo), "=f"(hi) : "l"(v));
}

// ---------------- encoder: conv1 + relu6 + conv2 + gumbel argmax ----------------
// grid 240 = 8 b * 30 chunks(32 t). block 256 = 32 t-lanes x 8 c-groups.
#define W2STRIDE 140                 // floats per channel row; 140 mod 32 = 12 -> conflict-free float4
#define W1STRIDE 14                  // even (8B-aligned pairs); banks distinct per cg
#define W2S_OFF 0
#define W1S_OFF (256 * W2STRIDE)
#define XS_OFF  (W1S_OFF + 256 * W1STRIDE)
#define B1S_OFF (XS_OFF + 32 * 50)
#define B2S_OFF (B1S_OFF + 256)
#define ENC_SMEM_FLOATS (B2S_OFF + 32)
#define ENC_SMEM_BYTES  (ENC_SMEM_FLOATS * 4)

__global__ __launch_bounds__(256, 1)
void k_encode(const float* __restrict__ x, const float* __restrict__ gumbel,
              const float* __restrict__ W1, const float* __restrict__ b1,
              const float* __restrict__ W2, const float* __restrict__ b2)
{
    extern __shared__ float sm[];
    float* W2s = sm + W2S_OFF;
    float* W1s = sm + W1S_OFF;
    float* xs  = sm + XS_OFF;
    float* b1s = sm + B1S_OFF;
    float* b2s = sm + B2S_OFF;

    const int tid = threadIdx.x;
    const int b   = blockIdx.x / 30;
    const int t0  = (blockIdx.x % 30) * 32;

    // stage weights (coalesced global reads; const-divisor index math)
    for (int lin = tid; lin < 28 * 256 * 5; lin += 256) {
        int o = lin / 1280, rem = lin % 1280;
        int c = rem / 5,    kk  = rem % 5;
        W2s[c * W2STRIDE + kk * 28 + o] = W2[lin];
    }
    for (int lin = tid; lin < 2560; lin += 256)
        W1s[(lin / 10) * W1STRIDE + (lin % 10)] = W1[lin];
    for (int lin = tid; lin < 32 * 50; lin += 256)
        xs[lin] = x[b * LL + t0 * 50 + lin];
    b1s[tid] = b1[tid];
    if (tid < 28) b2s[tid] = b2[tid];
    __syncthreads();

    const int tl = tid >> 3;      // local t (0..31)
    const int cg = tid & 7;       // channel group (0..7)
    const int t  = t0 + tl;

    // x window as 25 packed f32x2
    const unsigned long long* xs2 = (const unsigned long long*)(xs + tl * 50);
    unsigned long long xr2[25];
#pragma unroll
    for (int j = 0; j < 25; j++) xr2[j] = xs2[j];

    unsigned long long acc2[14];   // pairs of output channels (2j, 2j+1)
#pragma unroll
    for (int j = 0; j < 14; j++) acc2[j] = 0ULL;

#pragma unroll 2
    for (int ci = 0; ci < 32; ci++) {
        const int c = cg + 8 * ci;
        const unsigned long long* w1p = (const unsigned long long*)(W1s + c * W1STRIDE);
        const float b1c = b1s[c];
        float h[5];
#pragma unroll
        for (int kk = 0; kk < 5; kk++) {
            unsigned long long s2 = 0ULL;
#pragma unroll
            for (int k2 = 0; k2 < 5; k2++)
                fma2(s2, xr2[kk * 5 + k2], w1p[k2], s2);
            float lo, hi; unpack2(s2, lo, hi);
            float s = lo + hi + b1c;
            h[kk] = fminf(fmaxf(s, 0.f), 6.f);      // relu6
        }
        const float* wrow = &W2s[c * W2STRIDE];
#pragma unroll
        for (int kk = 0; kk < 5; kk++) {
            const unsigned long long hp = bcast2(h[kk]);
#pragma unroll
            for (int og = 0; og < 7; og++) {
                ulonglong2 w = *(const ulonglong2*)(wrow + kk * 28 + og * 4);
                fma2(acc2[og * 2 + 0], hp, w.x, acc2[og * 2 + 0]);
                fma2(acc2[og * 2 + 1], hp, w.y, acc2[og * 2 + 1]);
            }
        }
    }

    // reduce the 8 c-groups (lane bits 0..2), packed adds
#pragma unroll
    for (int j = 0; j < 14; j++) {
        unsigned long long v = acc2[j], o;
        o = __shfl_xor_sync(0xffffffffu, v, 1); add2(v, v, o);
        o = __shfl_xor_sync(0xffffffffu, v, 2); add2(v, v, o);
        o = __shfl_xor_sync(0xffffffffu, v, 4); add2(v, v, o);
        acc2[j] = v;
    }

    if (cg == 0) {
        float acc[28];
#pragma unroll
        for (int j = 0; j < 14; j++) unpack2(acc2[j], acc[2 * j], acc[2 * j + 1]);
        const float* g = gumbel + (b * TT + t) * VV;
        float best = -1e30f; int bi = 0;
#pragma unroll
        for (int o = 0; o < 28; o++) {
            float v = acc[o] + b2s[o] + g[o];
            if (v > best) { best = v; bi = o; }    // first-max = jnp.argmax
        }
        g_preds[b * TT + t] = bi;
    }
}

// ---------------- transpose Wd2 (C,Q,K1) -> [j][c][q], coalesced both sides ----------------
__global__ __launch_bounds__(256)
void k_transpose(const float* __restrict__ Wd2)
{
    __shared__ float tile[2560];
    const int c = blockIdx.x;
    for (int lin = threadIdx.x; lin < 2560; lin += 256)
        tile[lin] = Wd2[c * 2560 + lin];            // coalesced read
    __syncthreads();
    const int q = threadIdx.x;
#pragma unroll
    for (int j = 0; j < 10; j++)
        g_Wd2T[j * 65536 + c * 256 + q] = tile[q * 10 + j];  // coalesced write
}

// ---------------- decoder table: logprob[i][j2][j][q] = M + bd2 - LSE ----------------
// grid 290 = 29 i * 10 j, 256 threads (= q)
__global__ __launch_bounds__(256)
void k_table(const float* __restrict__ Wd1, const float* __restrict__ bd1,
             const float* __restrict__ bd2)
{
    __shared__ float rv[5 * 256];
    __shared__ float red[8];
    const int i   = blockIdx.x / 10;
    const int j   = blockIdx.x % 10;
    const int tid = threadIdx.x;

    // rv[j2][c] = clip(Wd1[i,c,j2] + bd1[c], 0, 6); i==28 is the masked (z=0) row
    for (int lin = tid; lin < 1280; lin += 256) {
        int c = lin / 5, j2 = lin % 5;
        float w = (i < VV) ? Wd1[i * 1280 + lin] : 0.f;
        rv[j2 * 256 + c] = fminf(fmaxf(w + bd1[c], 0.f), 6.f);
    }
    __syncthreads();

    float acc[5] = {0.f, 0.f, 0.f, 0.f, 0.f};
    const float* wt = g_Wd2T + j * 65536 + tid;     // coalesced across q
#pragma unroll 16
    for (int c = 0; c < 256; c++) {
        float w = wt[c * 256];
#pragma unroll
        for (int j2 = 0; j2 < 5; j2++)
            acc[j2] += rv[j2 * 256 + c] * w;
    }

    // LSE over q (threads) for each j2, then fold into stored table
    const float bdq  = bd2[tid];
    const int   lane = tid & 31, wid = tid >> 5;
    for (int j2 = 0; j2 < 5; j2++) {
        float v = acc[j2] + bdq;
        float m = v;
        for (int s = 16; s > 0; s >>= 1) m = fmaxf(m, __shfl_xor_sync(0xffffffffu, m, s));
        if (lane == 0) red[wid] = m;
        __syncthreads();
        float mAll = red[0];
#pragma unroll
        for (int w2 = 1; w2 < 8; w2++) mAll = fmaxf(mAll, red[w2]);
        __syncthreads();
        float e = expf(v - mAll);
        for (int s = 16; s > 0; s >>= 1) e += __shfl_xor_sync(0xffffffffu, e, s);
        if (lane == 0) red[wid] = e;
        __syncthreads();
        float ssum = 0.f;
#pragma unroll
        for (int w2 = 0; w2 < 8; w2++) ssum += red[w2];
        const float lse = mAll + logf(ssum);
        g_M[(((i * 5 + j2) * 10 + j) * 256) + tid] = v - lse;   // = acc + bd2 - LSE
        __syncthreads();
    }
}

// ---------------- loss: mu-law target + table gather (rec) + KL ----------------
__global__ __launch_bounds__(256)
void k_loss(const float* __restrict__ x, const int* __restrict__ x_sl,
            const float* __restrict__ ngrams)
{
    __shared__ double sr[8], sk[8];
    const int tid = threadIdx.x;
    const int gid = blockIdx.x * 256 + tid;         // < 384000 exactly
    const int b   = gid / LL, l = gid % LL;
    const int sl  = x_sl[b];
    const int zsl = sl / 50;
    const int t   = l / 50;

    float rec = 0.f, kl = 0.f;

    if (l < sl) {
        const float xv = x[gid];
        float y  = log1pf(255.f * fabsf(xv)) / 5.5451774444795625f;
        y = copysignf(y, xv);
        int tq = (int)floorf((y + 1.0f) * 0.5f * 256.0f);
        tq = min(max(tq, 0), 255);

        const int j2 = (l / 10) % 5;
        const int j  = l % 10;
        const int i  = (t < zsl) ? g_preds[b * TT + t] : 28;
        rec = -g_M[(((i * 5 + j2) * 10 + j) * 256) + tq];
    }

    if ((l % 50) == 0 && t < zsl) {
        const int p  = g_preds[b * TT + t];
        const int a0 = (t >= 2) ? g_preds[b * TT + t - 2] : 28;
        const int a1 = (t >= 1) ? g_preds[b * TT + t - 1] : 28;
        const float pr = ngrams[(a0 * 29 + a1) * 28 + p];
        kl = logf(1.0f / (pr + 1e-10f) + 1e-10f);
    }

    // float warp reduce, double at block level
    const int lane = tid & 31, wid = tid >> 5;
    for (int s = 16; s > 0; s >>= 1) {
        rec += __shfl_down_sync(0xffffffffu, rec, s);
        kl  += __shfl_down_sync(0xffffffffu, kl,  s);
    }
    if (lane == 0) { sr[wid] = (double)rec; sk[wid] = (double)kl; }
    __syncthreads();
    if (tid == 0) {
        double r = 0.0, k = 0.0;
#pragma unroll
        for (int w2 = 0; w2 < 8; w2++) { r += sr[w2]; k += sk[w2]; }
        g_prec[blockIdx.x] = r;
        g_pkl[blockIdx.x]  = k;
    }
}

// ---------------- final fixed-order reduction ----------------
__global__ __launch_bounds__(256)
void k_final(const int* __restrict__ x_sl, float* __restrict__ out)
{
    __shared__ double sr[8], sk[8];
    const int tid = threadIdx.x;
    double r = 0.0, k = 0.0;
    for (int i = tid; i < 1500; i += 256) { r += g_prec[i]; k += g_pkl[i]; }
    const int lane = tid & 31, wid = tid >> 5;
    for (int s = 16; s > 0; s >>= 1) {
        r += __shfl_down_sync(0xffffffffu, r, s);
        k += __shfl_down_sync(0xffffffffu, k, s);
    }
    if (lane == 0) { sr[wid] = r; sk[wid] = k; }
    __syncthreads();
    if (tid == 0) {
        double R = 0.0, K = 0.0;
#pragma unroll
        for (int w2 = 0; w2 < 8; w2++) { R += sr[w2]; K += sk[w2]; }
        long long sx = 0, sz = 0;
#pragma unroll
        for (int b = 0; b < BB; b++) { sx += x_sl[b]; sz += x_sl[b] / 50; }
        out[0] = (float)(R / (double)sx + K / (double)sz);
    }
}

// ---------------- launch ----------------
extern "C" void kernel_launch(void* const* d_in, const int* in_sizes, int n_in,
                              void* d_out, int out_size)
{
    const float* x      = (const float*)d_in[0];
    const int*   x_sl   = (const int*)  d_in[1];
    const float* ngrams = (const float*)d_in[4];
    const float* gumbel = (const float*)d_in[5];
    const float* W1     = (const float*)d_in[6];
    const float* b1     = (const float*)d_in[7];
    const float* W2     = (const float*)d_in[8];
    const float* b2     = (const float*)d_in[9];
    const float* Wd1    = (const float*)d_in[10];
    const float* bd1    = (const float*)d_in[11];
    const float* Wd2    = (const float*)d_in[12];
    const float* bd2    = (const float*)d_in[13];
    float* out = (float*)d_out;

    cudaFuncSetAttribute(k_encode, cudaFuncAttributeMaxDynamicSharedMemorySize,
                         ENC_SMEM_BYTES);

    k_encode<<<240, 256, ENC_SMEM_BYTES>>>(x, gumbel, W1, b1, W2, b2);
    k_transpose<<<256, 256>>>(Wd2);
    k_table<<<290, 256>>>(Wd1, bd1, bd2);
    k_loss<<<1500, 256>>>(x, x_sl, ngrams);
    k_final<<<1, 256>>>(x_sl, out);
}